// round 12
// baseline (speedup 1.0000x reference)
#include <cuda_runtime.h>

#define NN 100000
#define NE 1600000
#define FI 256
#define HD 32
#define AD 64
#define PD 512

// Scratch (device globals; no allocation allowed)
__device__ float g_buf1[NN * HD];
__device__ float g_buf2[NN * HD];
__device__ float g_dinv[NN];
__device__ int g_degi[NN];
__device__ int g_off[NN];
__device__ int g_cur[NN];
__device__ int g_csr[NE];
__device__ int g_bsum[128];
__device__ int g_boff[128];

#define NB_SCAN 98  // ceil(100000/1024)

typedef unsigned long long u64;

// ---- packed f32x2 helpers (FFMA2: 2 fp32 MACs per issue; PTX-only) -------
__device__ __forceinline__ u64 pk2(float lo, float hi) {
    u64 r;
    asm("mov.b64 %0, {%1, %2};" : "=l"(r) : "f"(lo), "f"(hi));
    return r;
}
__device__ __forceinline__ void fma2(u64& d, u64 a, u64 b) {
    asm("fma.rn.f32x2 %0, %1, %2, %0;" : "+l"(d) : "l"(a), "l"(b));
}
__device__ __forceinline__ float lohi(u64 v) {
    float lo, hi;
    asm("mov.b64 {%0, %1}, %2;" : "=f"(lo), "=f"(hi) : "l"(v));
    return lo + hi;
}

// ============================ CSR construction =============================
__global__ void k_zero() {
    int i = blockIdx.x * blockDim.x + threadIdx.x;
    if (i < NN) g_degi[i] = 0;
}

__global__ void k_hist(const int* __restrict__ dst) {
    int i = blockIdx.x * blockDim.x + threadIdx.x;
    if (i < NE) atomicAdd(&g_degi[dst[i]], 1);
}

__global__ void k_bsum() {
    __shared__ int sh[256];
    int b = blockIdx.x, t = threadIdx.x;
    int s = 0;
#pragma unroll
    for (int j = 0; j < 4; j++) {
        int i = b * 1024 + t + j * 256;
        if (i < NN) s += g_degi[i];
    }
    sh[t] = s;
    __syncthreads();
    for (int o = 128; o > 0; o >>= 1) {
        if (t < o) sh[t] += sh[t + o];
        __syncthreads();
    }
    if (t == 0) g_bsum[b] = sh[0];
}

__global__ void k_scanb() {
    __shared__ int sh[128];
    int t = threadIdx.x;
    int v = (t < NB_SCAN) ? g_bsum[t] : 0;
    sh[t] = v;
    __syncthreads();
#pragma unroll
    for (int o = 1; o < 128; o <<= 1) {
        int x = (t >= o) ? sh[t - o] : 0;
        __syncthreads();
        sh[t] += x;
        __syncthreads();
    }
    if (t < NB_SCAN) g_boff[t] = sh[t] - v;
}

__global__ void k_off() {
    __shared__ int sh[1024];
    int b = blockIdx.x, t = threadIdx.x;
    int i = b * 1024 + t;
    int v = (i < NN) ? g_degi[i] : 0;
    sh[t] = v;
    __syncthreads();
#pragma unroll
    for (int o = 1; o < 1024; o <<= 1) {
        int x = (t >= o) ? sh[t - o] : 0;
        __syncthreads();
        sh[t] += x;
        __syncthreads();
    }
    if (i < NN) {
        int off = g_boff[b] + sh[t] - v;
        g_off[i] = off;
        g_cur[i] = off;
    }
}

__global__ void k_dinv() {
    int i = blockIdx.x * blockDim.x + threadIdx.x;
    if (i < NN) g_dinv[i] = rsqrtf((float)g_degi[i] + 1.0f);  // +1 self loop
}

__global__ void k_fill(const int* __restrict__ src, const int* __restrict__ dst) {
    int i = blockIdx.x * blockDim.x + threadIdx.x;
    if (i < NE) {
        int pos = atomicAdd(&g_cur[dst[i]], 1);
        g_csr[pos] = src[i];
    }
}

// ---------------------------------------------------------------------------
// GEMM1: buf1 = (features @ W1) * dinv   (pre-scaled xs1)
// f32x2 everywhere: W1 k-pairs pre-packed in smem (u64); feature k-pairs read
// directly as LDS.64 (adjacent floats == ready f32x2, zero packing MOVs).
// Per k2: 1 w-LDS.64 + 4 p-LDS.64 + 4 FFMA2 = 9 issues / 8 MACs.
// ---------------------------------------------------------------------------
__global__ void __launch_bounds__(256) k_gemm1(const float* __restrict__ feat,
                                               const float* __restrict__ W1) {
    __shared__ u64 sWp[(FI / 2) * HD];  // 128x32 u64 = 32KB
    __shared__ float sF[32 * 68];       // 8.7KB (68 even -> 8B-aligned pairs)
    int t = threadIdx.x;
    // pack W1 pairs: sWp[k2*32+c] = (W1[2k2][c], W1[2k2+1][c])
    for (int idx = t; idx < (FI / 2) * HD; idx += 256) {
        int k2 = idx >> 5, c = idx & 31;
        sWp[idx] = pk2(__ldg(&W1[(2 * k2) * HD + c]), __ldg(&W1[(2 * k2 + 1) * HD + c]));
    }

    long long row0 = (long long)blockIdx.x * 32;
    int c = t & 31, rg = t >> 5;
    u64 A0 = 0, A1 = 0, A2 = 0, A3 = 0;

#pragma unroll
    for (int ch = 0; ch < 4; ch++) {
        __syncthreads();
#pragma unroll
        for (int u = 0; u < 2; u++) {
            int f = t + u * 256;
            int r = f >> 4, c4 = (f & 15) * 4;
            float4 v = __ldg((const float4*)(feat + (row0 + r) * FI + ch * 64 + c4));
            *(float4*)&sF[r * 68 + c4] = v;
        }
        __syncthreads();
#pragma unroll 8
        for (int k2 = 0; k2 < 32; k2++) {
            u64 w = sWp[(ch * 32 + k2) * HD + c];
            u64 pa = *(const u64*)&sF[rg * 68 + 2 * k2];
            u64 pb = *(const u64*)&sF[(rg + 8) * 68 + 2 * k2];
            u64 pc = *(const u64*)&sF[(rg + 16) * 68 + 2 * k2];
            u64 pd = *(const u64*)&sF[(rg + 24) * 68 + 2 * k2];
            fma2(A0, pa, w);
            fma2(A1, pb, w);
            fma2(A2, pc, w);
            fma2(A3, pd, w);
        }
    }
    float d0 = g_dinv[row0 + rg], d1 = g_dinv[row0 + rg + 8];
    float d2 = g_dinv[row0 + rg + 16], d3 = g_dinv[row0 + rg + 24];
    float* o = g_buf1 + row0 * HD;
    o[(rg) * HD + c] = lohi(A0) * d0;
    o[(rg + 8) * HD + c] = lohi(A1) * d1;
    o[(rg + 16) * HD + c] = lohi(A2) * d2;
    o[(rg + 24) * HD + c] = lohi(A3) * d3;
}

// ---------------------------------------------------------------------------
// Gather aggregation (NO atomics): one warp per node, lane = feature col.
// agg[n] = dinv[n] * ( xs[n] + sum_{s in N(n)} xs[s] )
// ---------------------------------------------------------------------------
__global__ void __launch_bounds__(256) k_gather() {
    const float* xs = g_buf1;
    float* agg = g_buf2;
    int node = blockIdx.x * 8 + (threadIdx.x >> 5);
    if (node >= NN) return;
    int c = threadIdx.x & 31;
    int off = g_off[node];
    int cnt = g_degi[node];
    float acc = xs[(long long)node * HD + c];
#pragma unroll 4
    for (int j = 0; j < cnt; j++) {
        int s = __ldg(&g_csr[off + j]);            // warp-broadcast load
        acc += __ldg(&xs[(long long)s * HD + c]);  // coalesced 128B row
    }
    agg[(long long)node * HD + c] = acc * g_dinv[node];
}

// ---------------------------------------------------------------------------
// GEMM2: x2 = relu(agg1 + b1) @ W2 ; buf1 = x2 * dinv (xs2)
// ---------------------------------------------------------------------------
__global__ void __launch_bounds__(256) k_gemm2(const float* __restrict__ W2,
                                               const float* __restrict__ b1) {
    __shared__ float sW[HD * HD];
    __shared__ float sH[64 * 33];
    int t = threadIdx.x;
    for (int i = t; i < HD * HD; i += 256) sW[i] = W2[i];
    int row0 = blockIdx.x * 64;
    for (int i = t; i < 64 * 32; i += 256) {
        int r = i >> 5, c = i & 31;
        int gr = row0 + r;
        sH[r * 33 + c] = (gr < NN) ? fmaxf(g_buf2[(long long)gr * HD + c] + b1[c], 0.f) : 0.f;
    }
    __syncthreads();
    int c = t & 31, rg = t >> 5;
    float acc[8];
#pragma unroll
    for (int i = 0; i < 8; i++) acc[i] = 0.f;
#pragma unroll
    for (int k = 0; k < HD; k++) {
        float w = sW[k * HD + c];
#pragma unroll
        for (int i = 0; i < 8; i++) acc[i] += sH[(rg + 8 * i) * 33 + k] * w;
    }
#pragma unroll
    for (int i = 0; i < 8; i++) {
        int gr = row0 + rg + 8 * i;
        if (gr < NN) g_buf1[(long long)gr * HD + c] = acc[i] * g_dinv[gr];
    }
}

// ---------------------------------------------------------------------------
// Head layer 1 (policy/value shared): sP = relu(sH @ W + b), f32x2 packed.
// ---------------------------------------------------------------------------
__device__ __forceinline__ void mlp_layer1(const float* __restrict__ W,
                                           const float* __restrict__ b,
                                           const float* sH, float* sP, int t) {
    const int j0 = t, j1 = t + 256;
    u64 w0p[16], w1p[16];
#pragma unroll
    for (int k2 = 0; k2 < 16; k2++) {
        w0p[k2] = pk2(__ldg(&W[(2 * k2) * PD + j0]), __ldg(&W[(2 * k2 + 1) * PD + j0]));
        w1p[k2] = pk2(__ldg(&W[(2 * k2) * PD + j1]), __ldg(&W[(2 * k2 + 1) * PD + j1]));
    }
    float bb0 = b[j0], bb1 = b[j1];
#pragma unroll 2
    for (int r = 0; r < 32; r++) {
        u64 s0 = pk2(bb0, 0.f), s1 = pk2(bb1, 0.f);
#pragma unroll
        for (int k2 = 0; k2 < 16; k2++) {
            u64 hp = *(const u64*)&sH[r * 34 + 2 * k2];
            fma2(s0, hp, w0p[k2]);
            fma2(s1, hp, w1p[k2]);
        }
        sP[r * 514 + j0] = fmaxf(lohi(s0), 0.f);
        sP[r * 514 + j1] = fmaxf(lohi(s1), 0.f);
    }
}

// ---------------------------------------------------------------------------
// Fused heads, 32-node tile, dynamic smem 84.5KB.
// Policy layer 2: pW2 staged PRE-PACKED as u64 k-pairs in 64-k chunks
// (transpose-pack in registers during the cooperative load). Per k2:
// 2 w-LDS.64 + 4 p-LDS.64 + 8 FFMA2 = 14 issues / 16 MACs.
// ---------------------------------------------------------------------------
__global__ void __launch_bounds__(256) k_head(
    const float* __restrict__ b2,
    const float* __restrict__ pW1, const float* __restrict__ pb1,
    const float* __restrict__ pW2, const float* __restrict__ pb2,
    const float* __restrict__ vW1, const float* __restrict__ vb1,
    const float* __restrict__ vW2, const float* __restrict__ vb2,
    float* __restrict__ out) {
    extern __shared__ float dsm[];
    float* sH = dsm;             // 32*34  = 1088 floats
    float* sP = dsm + 32 * 34;   // 32*514 = 16448 floats
    u64* sWp2 = (u64*)(dsm + 32 * 34 + 32 * 514);  // 32 k2 x 64 c u64 = 16KB
    float* sWv = (float*)sWp2;   // alias for vW2 staging
    const int t = threadIdx.x;
    const int n0 = blockIdx.x * 32;

    for (int i = t; i < 32 * 32; i += 256) {
        int r = i >> 5, c = i & 31;
        sH[r * 34 + c] = fmaxf(g_buf2[(long long)(n0 + r) * HD + c] + b2[c], 0.f);
    }
    __syncthreads();

    // ---- policy layer 1
    mlp_layer1(pW1, pb1, sH, sP, t);
    __syncthreads();

    // ---- policy layer 2: out = sP @ pW2 + pb2; 8 chunks of 64 k
    {
        int c = t & 31, rg = t >> 5;  // rows rg*4 .. rg*4+3
        u64 a0[4], a1[4];
        u64 i0 = pk2(pb2[c], 0.f), i1 = pk2(pb2[c + 32], 0.f);
#pragma unroll
        for (int i = 0; i < 4; i++) { a0[i] = i0; a1[i] = i1; }

        int sk2 = t >> 4, sc4 = (t & 15) * 4;  // staging coords
        for (int ch = 0; ch < 8; ch++) {
            // stage 64 k-rows of pW2, packed as (k even, k odd) u64 pairs
#pragma unroll
            for (int u = 0; u < 2; u++) {
                int k2 = sk2 + u * 16;  // 0..31 within chunk
                const float4 lo = __ldg((const float4*)&pW2[(ch * 64 + 2 * k2) * AD + sc4]);
                const float4 hi = __ldg((const float4*)&pW2[(ch * 64 + 2 * k2 + 1) * AD + sc4]);
                u64* w = &sWp2[k2 * 64 + sc4];
                w[0] = pk2(lo.x, hi.x);
                w[1] = pk2(lo.y, hi.y);
                w[2] = pk2(lo.z, hi.z);
                w[3] = pk2(lo.w, hi.w);
            }
            __syncthreads();
#pragma unroll
            for (int k2 = 0; k2 < 32; k2++) {
                int kk = ch * 64 + 2 * k2;
                u64 w0 = sWp2[k2 * 64 + c];
                u64 w1 = sWp2[k2 * 64 + 32 + c];
#pragma unroll
                for (int i = 0; i < 4; i++) {
                    u64 p = *(const u64*)&sP[(rg * 4 + i) * 514 + kk];
                    fma2(a0[i], p, w0);
                    fma2(a1[i], p, w1);
                }
            }
            __syncthreads();
        }
#pragma unroll
        for (int i = 0; i < 4; i++) {
            long long r = n0 + rg * 4 + i;
            out[r * AD + c] = lohi(a0[i]);
            out[r * AD + 32 + c] = lohi(a1[i]);
        }
    }
    __syncthreads();

    // ---- value layer 1
    mlp_layer1(vW1, vb1, sH, sP, t);

    // stage vW2 (512 floats) into sWv
    if (t < 128) *(float4*)&sWv[t * 4] = __ldg((const float4*)&vW2[t * 4]);
    __syncthreads();

    // ---- value layer 2: 8 warps x 4 rows; 8-lane strided dots + shfl reduce
    {
        int wid = t >> 5, l = t & 31;
        int row = wid * 4 + (l >> 3);
        int k0 = l & 7;
        float s = 0.f;
#pragma unroll
        for (int k = k0; k < PD; k += 8) s += sP[row * 514 + k] * sWv[k];
        s += __shfl_down_sync(0xffffffffu, s, 4);
        s += __shfl_down_sync(0xffffffffu, s, 2);
        s += __shfl_down_sync(0xffffffffu, s, 1);
        if (k0 == 0) out[(long long)NN * AD + n0 + row] = s + vb2[0];
    }
}

// ---------------------------------------------------------------------------
// Host side.
// ---------------------------------------------------------------------------
extern "C" void kernel_launch(void* const* d_in, const int* in_sizes, int n_in,
                              void* d_out, int out_size) {
    const float* feat = (const float*)d_in[0];
    const int* ei = (const int*)d_in[1];  // int32 (JAX x64-off)
    const float* W1 = (const float*)d_in[2];
    const float* b1 = (const float*)d_in[3];
    const float* W2 = (const float*)d_in[4];
    const float* b2 = (const float*)d_in[5];
    const float* pW1 = (const float*)d_in[6];
    const float* pb1 = (const float*)d_in[7];
    const float* pW2 = (const float*)d_in[8];
    const float* pb2 = (const float*)d_in[9];
    const float* vW1 = (const float*)d_in[10];
    const float* vb1 = (const float*)d_in[11];
    const float* vW2 = (const float*)d_in[12];
    const float* vb2 = (const float*)d_in[13];
    float* out = (float*)d_out;

    const int* src = ei;       // edge_index[0]
    const int* dst = ei + NE;  // edge_index[1]

    static int smem_set = 0;
    const int HEAD_SMEM = (32 * 34 + 32 * 514) * 4 + 32 * 64 * 8;  // 86528 B
    if (!smem_set) {
        cudaFuncSetAttribute(k_head, cudaFuncAttributeMaxDynamicSharedMemorySize,
                             HEAD_SMEM);
        smem_set = 1;
    }

    // ---- CSR build
    k_zero<<<(NN + 255) / 256, 256>>>();
    k_hist<<<(NE + 255) / 256, 256>>>(dst);
    k_bsum<<<NB_SCAN, 256>>>();
    k_scanb<<<1, 128>>>();
    k_off<<<NB_SCAN, 1024>>>();
    k_dinv<<<(NN + 255) / 256, 256>>>();
    k_fill<<<(NE + 255) / 256, 256>>>(src, dst);

    // ---- conv1: buf1 = xs1 ; buf2 = agg1 (gather)
    k_gemm1<<<NN / 32, 256>>>(feat, W1);
    k_gather<<<(NN + 7) / 8, 256>>>();

    // ---- conv2: buf1 = xs2 ; buf2 = agg2 (gather)
    k_gemm2<<<(NN + 63) / 64, 256>>>(W2, b1);
    k_gather<<<(NN + 7) / 8, 256>>>();

    // ---- heads (reads relu(buf2 + b2))
    k_head<<<NN / 32, 256, HEAD_SMEM>>>(b2, pW1, pb1, pW2, pb2, vW1, vb1, vW2,
                                        vb2, out);
}

// round 13
// speedup vs baseline: 1.4330x; 1.4330x over previous
#include <cuda_runtime.h>
#include <cstdint>

#define NN 100000
#define NE 1600000
#define FI 256
#define HD 32
#define AD 64
#define PD 512

// Scratch (device globals; no allocation allowed)
__device__ float g_buf1[NN * HD];
__device__ float g_buf2[NN * HD];
__device__ float g_dinv[NN];
__device__ int g_degi[NN];
__device__ int g_off[NN];
__device__ int g_cur[NN];
__device__ int g_csr[NE];
__device__ int g_bsum[128];
__device__ int g_boff[128];

#define NB_SCAN 98  // ceil(100000/1024)

typedef unsigned long long u64;
typedef unsigned int u32;

// ---- packed f32x2 helpers (FFMA2; PTX-only) -------------------------------
__device__ __forceinline__ u64 pk2(float lo, float hi) {
    u64 r;
    asm("mov.b64 %0, {%1, %2};" : "=l"(r) : "f"(lo), "f"(hi));
    return r;
}
__device__ __forceinline__ void fma2(u64& d, u64 a, u64 b) {
    asm("fma.rn.f32x2 %0, %1, %2, %0;" : "+l"(d) : "l"(a), "l"(b));
}
__device__ __forceinline__ float lohi(u64 v) {
    float lo, hi;
    asm("mov.b64 {%0, %1}, %2;" : "=f"(lo), "=f"(hi) : "l"(v));
    return lo + hi;
}

// ---- tf32 tensor-core helpers ---------------------------------------------
__device__ __forceinline__ u32 f2tf32(float f) {
    u32 u;
    asm("cvt.rna.tf32.f32 %0, %1;" : "=r"(u) : "f"(f));
    return u;
}
// D(16x8,f32) += A(16x8,tf32 row) * B(8x8,tf32 col)
__device__ __forceinline__ void mma8(float& c0, float& c1, float& c2, float& c3,
                                     u32 a0, u32 a1, u32 a2, u32 a3,
                                     u32 b0, u32 b1) {
    asm("mma.sync.aligned.m16n8k8.row.col.f32.tf32.tf32.f32 "
        "{%0,%1,%2,%3},{%4,%5,%6,%7},{%8,%9},{%0,%1,%2,%3};"
        : "+f"(c0), "+f"(c1), "+f"(c2), "+f"(c3)
        : "r"(a0), "r"(a1), "r"(a2), "r"(a3), "r"(b0), "r"(b1));
}

// ============================ CSR construction =============================
__global__ void k_zero() {
    int i = blockIdx.x * blockDim.x + threadIdx.x;
    if (i < NN) g_degi[i] = 0;
}

__global__ void k_hist(const int* __restrict__ dst) {
    int i = blockIdx.x * blockDim.x + threadIdx.x;
    if (i < NE) atomicAdd(&g_degi[dst[i]], 1);
}

__global__ void k_bsum() {
    __shared__ int sh[256];
    int b = blockIdx.x, t = threadIdx.x;
    int s = 0;
#pragma unroll
    for (int j = 0; j < 4; j++) {
        int i = b * 1024 + t + j * 256;
        if (i < NN) s += g_degi[i];
    }
    sh[t] = s;
    __syncthreads();
    for (int o = 128; o > 0; o >>= 1) {
        if (t < o) sh[t] += sh[t + o];
        __syncthreads();
    }
    if (t == 0) g_bsum[b] = sh[0];
}

__global__ void k_scanb() {
    __shared__ int sh[128];
    int t = threadIdx.x;
    int v = (t < NB_SCAN) ? g_bsum[t] : 0;
    sh[t] = v;
    __syncthreads();
#pragma unroll
    for (int o = 1; o < 128; o <<= 1) {
        int x = (t >= o) ? sh[t - o] : 0;
        __syncthreads();
        sh[t] += x;
        __syncthreads();
    }
    if (t < NB_SCAN) g_boff[t] = sh[t] - v;
}

__global__ void k_off() {
    __shared__ int sh[1024];
    int b = blockIdx.x, t = threadIdx.x;
    int i = b * 1024 + t;
    int v = (i < NN) ? g_degi[i] : 0;
    sh[t] = v;
    __syncthreads();
#pragma unroll
    for (int o = 1; o < 1024; o <<= 1) {
        int x = (t >= o) ? sh[t - o] : 0;
        __syncthreads();
        sh[t] += x;
        __syncthreads();
    }
    if (i < NN) {
        int off = g_boff[b] + sh[t] - v;
        g_off[i] = off;
        g_cur[i] = off;
    }
}

__global__ void k_dinv() {
    int i = blockIdx.x * blockDim.x + threadIdx.x;
    if (i < NN) g_dinv[i] = rsqrtf((float)g_degi[i] + 1.0f);  // +1 self loop
}

__global__ void k_fill(const int* __restrict__ src, const int* __restrict__ dst) {
    int i = blockIdx.x * blockDim.x + threadIdx.x;
    if (i < NE) {
        int pos = atomicAdd(&g_cur[dst[i]], 1);
        g_csr[pos] = src[i];
    }
}

// ---------------------------------------------------------------------------
// GEMM1: buf1 = (features @ W1) * dinv   (pre-scaled xs1), f32x2 packed.
// ---------------------------------------------------------------------------
__global__ void __launch_bounds__(256) k_gemm1(const float* __restrict__ feat,
                                               const float* __restrict__ W1) {
    __shared__ u64 sWp[(FI / 2) * HD];  // 32KB
    __shared__ float sF[32 * 68];       // 8.7KB
    int t = threadIdx.x;
    for (int idx = t; idx < (FI / 2) * HD; idx += 256) {
        int k2 = idx >> 5, c = idx & 31;
        sWp[idx] = pk2(__ldg(&W1[(2 * k2) * HD + c]), __ldg(&W1[(2 * k2 + 1) * HD + c]));
    }

    long long row0 = (long long)blockIdx.x * 32;
    int c = t & 31, rg = t >> 5;
    u64 A0 = 0, A1 = 0, A2 = 0, A3 = 0;

#pragma unroll
    for (int ch = 0; ch < 4; ch++) {
        __syncthreads();
#pragma unroll
        for (int u = 0; u < 2; u++) {
            int f = t + u * 256;
            int r = f >> 4, c4 = (f & 15) * 4;
            float4 v = __ldg((const float4*)(feat + (row0 + r) * FI + ch * 64 + c4));
            *(float4*)&sF[r * 68 + c4] = v;
        }
        __syncthreads();
#pragma unroll 8
        for (int k2 = 0; k2 < 32; k2++) {
            u64 w = sWp[(ch * 32 + k2) * HD + c];
            u64 pa = *(const u64*)&sF[rg * 68 + 2 * k2];
            u64 pb = *(const u64*)&sF[(rg + 8) * 68 + 2 * k2];
            u64 pc = *(const u64*)&sF[(rg + 16) * 68 + 2 * k2];
            u64 pd = *(const u64*)&sF[(rg + 24) * 68 + 2 * k2];
            fma2(A0, pa, w);
            fma2(A1, pb, w);
            fma2(A2, pc, w);
            fma2(A3, pd, w);
        }
    }
    float d0 = g_dinv[row0 + rg], d1 = g_dinv[row0 + rg + 8];
    float d2 = g_dinv[row0 + rg + 16], d3 = g_dinv[row0 + rg + 24];
    float* o = g_buf1 + row0 * HD;
    o[(rg) * HD + c] = lohi(A0) * d0;
    o[(rg + 8) * HD + c] = lohi(A1) * d1;
    o[(rg + 16) * HD + c] = lohi(A2) * d2;
    o[(rg + 24) * HD + c] = lohi(A3) * d3;
}

// ---------------------------------------------------------------------------
// Gather aggregation (NO atomics): one warp per node, lane = feature col.
// ---------------------------------------------------------------------------
__global__ void __launch_bounds__(256) k_gather() {
    const float* xs = g_buf1;
    float* agg = g_buf2;
    int node = blockIdx.x * 8 + (threadIdx.x >> 5);
    if (node >= NN) return;
    int c = threadIdx.x & 31;
    int off = g_off[node];
    int cnt = g_degi[node];
    float acc = xs[(long long)node * HD + c];
#pragma unroll 4
    for (int j = 0; j < cnt; j++) {
        int s = __ldg(&g_csr[off + j]);
        acc += __ldg(&xs[(long long)s * HD + c]);
    }
    agg[(long long)node * HD + c] = acc * g_dinv[node];
}

// ---------------------------------------------------------------------------
// GEMM2: x2 = relu(agg1 + b1) @ W2 ; buf1 = x2 * dinv (xs2)
// ---------------------------------------------------------------------------
__global__ void __launch_bounds__(256) k_gemm2(const float* __restrict__ W2,
                                               const float* __restrict__ b1) {
    __shared__ float sW[HD * HD];
    __shared__ float sH[64 * 33];
    int t = threadIdx.x;
    for (int i = t; i < HD * HD; i += 256) sW[i] = W2[i];
    int row0 = blockIdx.x * 64;
    for (int i = t; i < 64 * 32; i += 256) {
        int r = i >> 5, c = i & 31;
        int gr = row0 + r;
        sH[r * 33 + c] = (gr < NN) ? fmaxf(g_buf2[(long long)gr * HD + c] + b1[c], 0.f) : 0.f;
    }
    __syncthreads();
    int c = t & 31, rg = t >> 5;
    float acc[8];
#pragma unroll
    for (int i = 0; i < 8; i++) acc[i] = 0.f;
#pragma unroll
    for (int k = 0; k < HD; k++) {
        float w = sW[k * HD + c];
#pragma unroll
        for (int i = 0; i < 8; i++) acc[i] += sH[(rg + 8 * i) * 33 + k] * w;
    }
#pragma unroll
    for (int i = 0; i < 8; i++) {
        int gr = row0 + rg + 8 * i;
        if (gr < NN) g_buf1[(long long)gr * HD + c] = acc[i] * g_dinv[gr];
    }
}

// ---------------------------------------------------------------------------
// Head layer 1 via tf32 mma: sP = relu(sH @ W + b), outputs stored as
// tf32-bit floats. Warp w owns n in [w*64, w*64+64). A fragments hoisted.
// sH stride 36, sP stride 516 -> conflict-free fragment LDS.
// ---------------------------------------------------------------------------
__device__ __forceinline__ void head_l1_mma(const float* __restrict__ W,
                                            const float* __restrict__ b,
                                            const u32* sH, float* sP,
                                            int w, int g, int tg) {
    // hoist A fragments: [m][kb][4]
    u32 A[2][4][4];
#pragma unroll
    for (int m = 0; m < 2; m++)
#pragma unroll
        for (int kb = 0; kb < 4; kb++) {
            int r = m * 16 + g, k = kb * 8 + tg;
            A[m][kb][0] = sH[r * 36 + k];
            A[m][kb][1] = sH[(r + 8) * 36 + k];
            A[m][kb][2] = sH[r * 36 + k + 4];
            A[m][kb][3] = sH[(r + 8) * 36 + k + 4];
        }
#pragma unroll
    for (int nb = 0; nb < 8; nb++) {
        int n = w * 64 + nb * 8 + g;
        u32 B[4][2];
#pragma unroll
        for (int kb = 0; kb < 4; kb++) {
            B[kb][0] = f2tf32(__ldg(&W[(kb * 8 + tg) * PD + n]));
            B[kb][1] = f2tf32(__ldg(&W[(kb * 8 + tg + 4) * PD + n]));
        }
        float2 bias = *(const float2*)&b[w * 64 + nb * 8 + 2 * tg];
        int col = w * 64 + nb * 8 + 2 * tg;
#pragma unroll
        for (int m = 0; m < 2; m++) {
            float c0 = 0.f, c1 = 0.f, c2 = 0.f, c3 = 0.f;
#pragma unroll
            for (int kb = 0; kb < 4; kb++)
                mma8(c0, c1, c2, c3, A[m][kb][0], A[m][kb][1], A[m][kb][2],
                     A[m][kb][3], B[kb][0], B[kb][1]);
            float2 lo, hi;
            lo.x = __uint_as_float(f2tf32(fmaxf(c0 + bias.x, 0.f)));
            lo.y = __uint_as_float(f2tf32(fmaxf(c1 + bias.y, 0.f)));
            hi.x = __uint_as_float(f2tf32(fmaxf(c2 + bias.x, 0.f)));
            hi.y = __uint_as_float(f2tf32(fmaxf(c3 + bias.y, 0.f)));
            int r = m * 16 + g;
            *(float2*)&sP[r * 516 + col] = lo;
            *(float2*)&sP[(r + 8) * 516 + col] = hi;
        }
    }
}

// ---------------------------------------------------------------------------
// Fused heads, 32-node tile, tf32 tensor cores. dyn smem 70.7KB (2 CTA/SM).
// ---------------------------------------------------------------------------
__global__ void __launch_bounds__(256) k_head(
    const float* __restrict__ b2,
    const float* __restrict__ pW1, const float* __restrict__ pb1,
    const float* __restrict__ pW2, const float* __restrict__ pb2,
    const float* __restrict__ vW1, const float* __restrict__ vb1,
    const float* __restrict__ vW2, const float* __restrict__ vb2,
    float* __restrict__ out) {
    extern __shared__ float dsm[];
    u32* sH = (u32*)dsm;         // 32*36 u32
    float* sP = dsm + 32 * 36;   // 32*516 floats
    const int t = threadIdx.x;
    const int n0 = blockIdx.x * 32;
    const int w = t >> 5, lane = t & 31, g = lane >> 2, tg = lane & 3;

    // load h2 = relu(buf2 + b2), convert to tf32 bits
    for (int i = t; i < 32 * 32; i += 256) {
        int r = i >> 5, c = i & 31;
        sH[r * 36 + c] =
            f2tf32(fmaxf(g_buf2[(long long)(n0 + r) * HD + c] + b2[c], 0.f));
    }
    __syncthreads();

    // ---- policy layer 1 (tensor)
    head_l1_mma(pW1, pb1, sH, sP, w, g, tg);
    __syncthreads();

    // ---- policy layer 2 (tensor): out = sP @ pW2 + pb2
    // warp w owns n8 tile [w*8, w*8+8); K = 64 kb steps
    {
        float c[2][4];
#pragma unroll
        for (int m = 0; m < 2; m++)
#pragma unroll
            for (int i = 0; i < 4; i++) c[m][i] = 0.f;
#pragma unroll 4
        for (int kb = 0; kb < 64; kb++) {
            u32 b0 = f2tf32(__ldg(&pW2[(kb * 8 + tg) * AD + w * 8 + g]));
            u32 b1 = f2tf32(__ldg(&pW2[(kb * 8 + tg + 4) * AD + w * 8 + g]));
            int k = kb * 8 + tg;
#pragma unroll
            for (int m = 0; m < 2; m++) {
                int r = m * 16 + g;
                u32 a0 = __float_as_uint(sP[r * 516 + k]);
                u32 a1 = __float_as_uint(sP[(r + 8) * 516 + k]);
                u32 a2 = __float_as_uint(sP[r * 516 + k + 4]);
                u32 a3 = __float_as_uint(sP[(r + 8) * 516 + k + 4]);
                mma8(c[m][0], c[m][1], c[m][2], c[m][3], a0, a1, a2, a3, b0, b1);
            }
        }
        float2 bias = *(const float2*)&pb2[w * 8 + 2 * tg];
        int col = w * 8 + 2 * tg;
#pragma unroll
        for (int m = 0; m < 2; m++) {
            long long r = n0 + m * 16 + g;
            float2 lo, hi;
            lo.x = c[m][0] + bias.x;
            lo.y = c[m][1] + bias.y;
            hi.x = c[m][2] + bias.x;
            hi.y = c[m][3] + bias.y;
            *(float2*)&out[r * AD + col] = lo;
            *(float2*)&out[(r + 8) * AD + col] = hi;
        }
    }
    __syncthreads();

    // ---- value layer 1 (tensor, overwrites sP)
    head_l1_mma(vW1, vb1, sH, sP, w, g, tg);
    __syncthreads();

    // ---- value layer 2: 8 warps x 4 rows; 8-lane strided dots + shfl reduce
    {
        int row = w * 4 + (lane >> 3);
        int k0 = lane & 7;
        float s = 0.f;
#pragma unroll
        for (int k = k0; k < PD; k += 8) s += sP[row * 516 + k] * __ldg(&vW2[k]);
        s += __shfl_down_sync(0xffffffffu, s, 4);
        s += __shfl_down_sync(0xffffffffu, s, 2);
        s += __shfl_down_sync(0xffffffffu, s, 1);
        if (k0 == 0) out[(long long)NN * AD + n0 + row] = s + __ldg(&vb2[0]);
    }
}

// ---------------------------------------------------------------------------
// Host side.
// ---------------------------------------------------------------------------
extern "C" void kernel_launch(void* const* d_in, const int* in_sizes, int n_in,
                              void* d_out, int out_size) {
    const float* feat = (const float*)d_in[0];
    const int* ei = (const int*)d_in[1];  // int32 (JAX x64-off)
    const float* W1 = (const float*)d_in[2];
    const float* b1 = (const float*)d_in[3];
    const float* W2 = (const float*)d_in[4];
    const float* b2 = (const float*)d_in[5];
    const float* pW1 = (const float*)d_in[6];
    const float* pb1 = (const float*)d_in[7];
    const float* pW2 = (const float*)d_in[8];
    const float* pb2 = (const float*)d_in[9];
    const float* vW1 = (const float*)d_in[10];
    const float* vb1 = (const float*)d_in[11];
    const float* vW2 = (const float*)d_in[12];
    const float* vb2 = (const float*)d_in[13];
    float* out = (float*)d_out;

    const int* src = ei;       // edge_index[0]
    const int* dst = ei + NE;  // edge_index[1]

    static int smem_set = 0;
    const int HEAD_SMEM = (32 * 36 + 32 * 516) * 4;  // 70656 B
    if (!smem_set) {
        cudaFuncSetAttribute(k_head, cudaFuncAttributeMaxDynamicSharedMemorySize,
                             HEAD_SMEM);
        smem_set = 1;
    }

    // ---- CSR build
    k_zero<<<(NN + 255) / 256, 256>>>();
    k_hist<<<(NE + 255) / 256, 256>>>(dst);
    k_bsum<<<NB_SCAN, 256>>>();
    k_scanb<<<1, 128>>>();
    k_off<<<NB_SCAN, 1024>>>();
    k_dinv<<<(NN + 255) / 256, 256>>>();
    k_fill<<<(NE + 255) / 256, 256>>>(src, dst);

    // ---- conv1: buf1 = xs1 ; buf2 = agg1 (gather)
    k_gemm1<<<NN / 32, 256>>>(feat, W1);
    k_gather<<<(NN + 7) / 8, 256>>>();

    // ---- conv2: buf1 = xs2 ; buf2 = agg2 (gather)
    k_gemm2<<<(NN + 63) / 64, 256>>>(W2, b1);
    k_gather<<<(NN + 7) / 8, 256>>>();

    // ---- heads (tf32 tensor cores; reads relu(buf2 + b2))
    k_head<<<NN / 32, 256, HEAD_SMEM>>>(b2, pW1, pb1, pW2, pb2, vW1, vb1, vW2,
                                        vb2, out);
}

// round 14
// speedup vs baseline: 1.4930x; 1.0418x over previous
#include <cuda_runtime.h>
#include <cstdint>

#define NN 100000
#define NE 1600000
#define FI 256
#define HD 32
#define AD 64
#define PD 512

// Scratch (device globals; no allocation allowed)
__device__ float g_buf1[NN * HD];
__device__ float g_buf2[NN * HD];
__device__ float g_dinv[NN];
__device__ int g_degi[NN];
__device__ int g_off[NN];
__device__ int g_cur[NN];
__device__ int g_csr[NE];
__device__ int g_bsum[128];
__device__ int g_boff[128];
// pre-converted tf32 weight bits (head)
__device__ unsigned int g_pW1t[HD * PD];
__device__ unsigned int g_pW2t[PD * AD];
__device__ unsigned int g_vW1t[HD * PD];

#define NB_SCAN 98  // ceil(100000/1024)

typedef unsigned long long u64;
typedef unsigned int u32;

// ---- packed f32x2 helpers (FFMA2; PTX-only) -------------------------------
__device__ __forceinline__ u64 pk2(float lo, float hi) {
    u64 r;
    asm("mov.b64 %0, {%1, %2};" : "=l"(r) : "f"(lo), "f"(hi));
    return r;
}
__device__ __forceinline__ void fma2(u64& d, u64 a, u64 b) {
    asm("fma.rn.f32x2 %0, %1, %2, %0;" : "+l"(d) : "l"(a), "l"(b));
}
__device__ __forceinline__ float lohi(u64 v) {
    float lo, hi;
    asm("mov.b64 {%0, %1}, %2;" : "=f"(lo), "=f"(hi) : "l"(v));
    return lo + hi;
}

// ---- tf32 tensor-core helpers ---------------------------------------------
__device__ __forceinline__ u32 f2tf32(float f) {
    u32 u;
    asm("cvt.rna.tf32.f32 %0, %1;" : "=r"(u) : "f"(f));
    return u;
}
__device__ __forceinline__ void mma8(float& c0, float& c1, float& c2, float& c3,
                                     u32 a0, u32 a1, u32 a2, u32 a3,
                                     u32 b0, u32 b1) {
    asm("mma.sync.aligned.m16n8k8.row.col.f32.tf32.tf32.f32 "
        "{%0,%1,%2,%3},{%4,%5,%6,%7},{%8,%9},{%0,%1,%2,%3};"
        : "+f"(c0), "+f"(c1), "+f"(c2), "+f"(c3)
        : "r"(a0), "r"(a1), "r"(a2), "r"(a3), "r"(b0), "r"(b1));
}

// ============================ CSR construction =============================
__global__ void k_zero() {
    int i = blockIdx.x * blockDim.x + threadIdx.x;
    if (i < NN) g_degi[i] = 0;
}

__global__ void k_hist(const int* __restrict__ dst) {
    int i = blockIdx.x * blockDim.x + threadIdx.x;
    if (i < NE) atomicAdd(&g_degi[dst[i]], 1);
}

__global__ void k_bsum() {
    __shared__ int sh[256];
    int b = blockIdx.x, t = threadIdx.x;
    int s = 0;
#pragma unroll
    for (int j = 0; j < 4; j++) {
        int i = b * 1024 + t + j * 256;
        if (i < NN) s += g_degi[i];
    }
    sh[t] = s;
    __syncthreads();
    for (int o = 128; o > 0; o >>= 1) {
        if (t < o) sh[t] += sh[t + o];
        __syncthreads();
    }
    if (t == 0) g_bsum[b] = sh[0];
}

__global__ void k_scanb() {
    __shared__ int sh[128];
    int t = threadIdx.x;
    int v = (t < NB_SCAN) ? g_bsum[t] : 0;
    sh[t] = v;
    __syncthreads();
#pragma unroll
    for (int o = 1; o < 128; o <<= 1) {
        int x = (t >= o) ? sh[t - o] : 0;
        __syncthreads();
        sh[t] += x;
        __syncthreads();
    }
    if (t < NB_SCAN) g_boff[t] = sh[t] - v;
}

// per-chunk exclusive scan + chunk base -> offsets & cursors; fused dinv.
__global__ void k_off() {
    __shared__ int sh[1024];
    int b = blockIdx.x, t = threadIdx.x;
    int i = b * 1024 + t;
    int v = (i < NN) ? g_degi[i] : 0;
    sh[t] = v;
    __syncthreads();
#pragma unroll
    for (int o = 1; o < 1024; o <<= 1) {
        int x = (t >= o) ? sh[t - o] : 0;
        __syncthreads();
        sh[t] += x;
        __syncthreads();
    }
    if (i < NN) {
        int off = g_boff[b] + sh[t] - v;
        g_off[i] = off;
        g_cur[i] = off;
        g_dinv[i] = rsqrtf((float)v + 1.0f);  // +1 self loop
    }
}

__global__ void k_fill(const int* __restrict__ src, const int* __restrict__ dst) {
    int i = blockIdx.x * blockDim.x + threadIdx.x;
    if (i < NE) {
        int pos = atomicAdd(&g_cur[dst[i]], 1);
        g_csr[pos] = src[i];
    }
}

// Pre-convert head weights to tf32 bits (once per call; weights block-invariant)
__global__ void k_cvtw(const float* __restrict__ pW1, const float* __restrict__ pW2,
                       const float* __restrict__ vW1) {
    int i = blockIdx.x * blockDim.x + threadIdx.x;
    if (i < HD * PD) {
        g_pW1t[i] = f2tf32(pW1[i]);
        g_vW1t[i] = f2tf32(vW1[i]);
    }
    if (i < PD * AD) g_pW2t[i] = f2tf32(pW2[i]);
}

// ---------------------------------------------------------------------------
// GEMM1: buf1 = (features @ W1) * dinv   (pre-scaled xs1), f32x2 packed.
// 64 rows/block, 8 rows/warp: weight LDS.64 (2wf) amortized over 8 broadcast
// feature pairs -> 10wf / 512 MACs on the crossbar.
// ---------------------------------------------------------------------------
__global__ void __launch_bounds__(256) k_gemm1(const float* __restrict__ feat,
                                               const float* __restrict__ W1) {
    __shared__ u64 sWp[(FI / 2) * HD];  // 32KB
    __shared__ float sF[64 * 36];       // 9.2KB (36 even -> aligned pairs)
    int t = threadIdx.x;
    for (int idx = t; idx < (FI / 2) * HD; idx += 256) {
        int k2 = idx >> 5, c = idx & 31;
        sWp[idx] = pk2(__ldg(&W1[(2 * k2) * HD + c]), __ldg(&W1[(2 * k2 + 1) * HD + c]));
    }

    long long row0 = (long long)blockIdx.x * 64;
    int c = t & 31, w = t >> 5;
    u64 A[8];
#pragma unroll
    for (int i = 0; i < 8; i++) A[i] = 0;

#pragma unroll
    for (int ch = 0; ch < 8; ch++) {  // 8 chunks of 32 cols
        __syncthreads();
#pragma unroll
        for (int u = 0; u < 2; u++) {
            int f = t + u * 256;  // float4 idx 0..511
            int r = f >> 3, c4 = (f & 7) * 4;
            long long gr = row0 + r;
            if (gr >= NN) gr = NN - 1;  // clamp (stores guarded later)
            *(float4*)&sF[r * 36 + c4] = __ldg((const float4*)(feat + gr * FI + ch * 32 + c4));
        }
        __syncthreads();
#pragma unroll 8
        for (int k2 = 0; k2 < 16; k2++) {
            u64 wv = sWp[(ch * 16 + k2) * HD + c];
#pragma unroll
            for (int i = 0; i < 8; i++) {
                u64 p = *(const u64*)&sF[(w + 8 * i) * 36 + 2 * k2];  // broadcast
                fma2(A[i], p, wv);
            }
        }
    }
#pragma unroll
    for (int i = 0; i < 8; i++) {
        long long row = row0 + w + 8 * i;
        if (row < NN) g_buf1[row * HD + c] = lohi(A[i]) * g_dinv[row];
    }
}

// ---------------------------------------------------------------------------
// Gather aggregation: HALF-warp per node (16 lanes x float2 = 128B row),
// 4-deep index prefetch + split accumulators -> MLP>=4 per chain.
// agg[n] = dinv[n] * ( xs[n] + sum_{s in N(n)} xs[s] )
// ---------------------------------------------------------------------------
__global__ void __launch_bounds__(256) k_gather() {
    const float2* xs = (const float2*)g_buf1;
    float2* agg = (float2*)g_buf2;
    int node = blockIdx.x * 16 + (threadIdx.x >> 4);
    if (node >= NN) return;
    int c2 = threadIdx.x & 15;
    int off = g_off[node];
    int cnt = g_degi[node];
    float2 a0 = xs[node * 16 + c2];
    float2 a1 = make_float2(0.f, 0.f);
    int j = 0;
    for (; j + 4 <= cnt; j += 4) {
        int s0 = __ldg(&g_csr[off + j]);
        int s1 = __ldg(&g_csr[off + j + 1]);
        int s2 = __ldg(&g_csr[off + j + 2]);
        int s3 = __ldg(&g_csr[off + j + 3]);
        float2 v0 = __ldg(&xs[s0 * 16 + c2]);
        float2 v1 = __ldg(&xs[s1 * 16 + c2]);
        float2 v2 = __ldg(&xs[s2 * 16 + c2]);
        float2 v3 = __ldg(&xs[s3 * 16 + c2]);
        a0.x += v0.x + v1.x;
        a0.y += v0.y + v1.y;
        a1.x += v2.x + v3.x;
        a1.y += v2.y + v3.y;
    }
    for (; j < cnt; j++) {
        int s = __ldg(&g_csr[off + j]);
        float2 v = __ldg(&xs[s * 16 + c2]);
        a0.x += v.x;
        a0.y += v.y;
    }
    float dv = g_dinv[node];
    agg[node * 16 + c2] = make_float2((a0.x + a1.x) * dv, (a0.y + a1.y) * dv);
}

// ---------------------------------------------------------------------------
// GEMM2: x2 = relu(agg1 + b1) @ W2 ; buf1 = x2 * dinv (xs2)
// ---------------------------------------------------------------------------
__global__ void __launch_bounds__(256) k_gemm2(const float* __restrict__ W2,
                                               const float* __restrict__ b1) {
    __shared__ float sW[HD * HD];
    __shared__ float sH[64 * 33];
    int t = threadIdx.x;
    for (int i = t; i < HD * HD; i += 256) sW[i] = W2[i];
    int row0 = blockIdx.x * 64;
    for (int i = t; i < 64 * 32; i += 256) {
        int r = i >> 5, c = i & 31;
        int gr = row0 + r;
        sH[r * 33 + c] = (gr < NN) ? fmaxf(g_buf2[(long long)gr * HD + c] + b1[c], 0.f) : 0.f;
    }
    __syncthreads();
    int c = t & 31, rg = t >> 5;
    float acc[8];
#pragma unroll
    for (int i = 0; i < 8; i++) acc[i] = 0.f;
#pragma unroll
    for (int k = 0; k < HD; k++) {
        float w = sW[k * HD + c];
#pragma unroll
        for (int i = 0; i < 8; i++) acc[i] += sH[(rg + 8 * i) * 33 + k] * w;
    }
#pragma unroll
    for (int i = 0; i < 8; i++) {
        int gr = row0 + rg + 8 * i;
        if (gr < NN) g_buf1[(long long)gr * HD + c] = acc[i] * g_dinv[gr];
    }
}

// ---------------------------------------------------------------------------
// Head layer 1 via tf32 mma: sP = relu(sH @ W + b), W pre-converted (u32).
// Warp w owns n in [w*64, w*64+64). A fragments hoisted.
// ---------------------------------------------------------------------------
__device__ __forceinline__ void head_l1_mma(const u32* __restrict__ Wt,
                                            const float* __restrict__ b,
                                            const u32* sH, float* sP,
                                            int w, int g, int tg) {
    u32 A[2][4][4];
#pragma unroll
    for (int m = 0; m < 2; m++)
#pragma unroll
        for (int kb = 0; kb < 4; kb++) {
            int r = m * 16 + g, k = kb * 8 + tg;
            A[m][kb][0] = sH[r * 36 + k];
            A[m][kb][1] = sH[(r + 8) * 36 + k];
            A[m][kb][2] = sH[r * 36 + k + 4];
            A[m][kb][3] = sH[(r + 8) * 36 + k + 4];
        }
#pragma unroll
    for (int nb = 0; nb < 8; nb++) {
        int n = w * 64 + nb * 8 + g;
        u32 B[4][2];
#pragma unroll
        for (int kb = 0; kb < 4; kb++) {
            B[kb][0] = __ldg(&Wt[(kb * 8 + tg) * PD + n]);
            B[kb][1] = __ldg(&Wt[(kb * 8 + tg + 4) * PD + n]);
        }
        float2 bias = *(const float2*)&b[w * 64 + nb * 8 + 2 * tg];
        int col = w * 64 + nb * 8 + 2 * tg;
#pragma unroll
        for (int m = 0; m < 2; m++) {
            float c0 = 0.f, c1 = 0.f, c2 = 0.f, c3 = 0.f;
#pragma unroll
            for (int kb = 0; kb < 4; kb++)
                mma8(c0, c1, c2, c3, A[m][kb][0], A[m][kb][1], A[m][kb][2],
                     A[m][kb][3], B[kb][0], B[kb][1]);
            float2 lo, hi;
            lo.x = __uint_as_float(f2tf32(fmaxf(c0 + bias.x, 0.f)));
            lo.y = __uint_as_float(f2tf32(fmaxf(c1 + bias.y, 0.f)));
            hi.x = __uint_as_float(f2tf32(fmaxf(c2 + bias.x, 0.f)));
            hi.y = __uint_as_float(f2tf32(fmaxf(c3 + bias.y, 0.f)));
            int r = m * 16 + g;
            *(float2*)&sP[r * 516 + col] = lo;
            *(float2*)&sP[(r + 8) * 516 + col] = hi;
        }
    }
}

// ---------------------------------------------------------------------------
// Fused heads, 32-node tile, tf32 tensor cores. dyn smem 70.7KB (2 CTA/SM).
// ---------------------------------------------------------------------------
__global__ void __launch_bounds__(256) k_head(
    const float* __restrict__ b2,
    const float* __restrict__ pb1, const float* __restrict__ pb2,
    const float* __restrict__ vb1,
    const float* __restrict__ vW2, const float* __restrict__ vb2,
    float* __restrict__ out) {
    extern __shared__ float dsm[];
    u32* sH = (u32*)dsm;        // 32*36 u32
    float* sP = dsm + 32 * 36;  // 32*516 floats
    const int t = threadIdx.x;
    const int n0 = blockIdx.x * 32;
    const int w = t >> 5, lane = t & 31, g = lane >> 2, tg = lane & 3;

    for (int i = t; i < 32 * 32; i += 256) {
        int r = i >> 5, c = i & 31;
        sH[r * 36 + c] =
            f2tf32(fmaxf(g_buf2[(long long)(n0 + r) * HD + c] + b2[c], 0.f));
    }
    __syncthreads();

    // ---- policy layer 1 (tensor)
    head_l1_mma(g_pW1t, pb1, sH, sP, w, g, tg);
    __syncthreads();

    // ---- policy layer 2 (tensor): out = sP @ pW2 + pb2
    {
        float c[2][4];
#pragma unroll
        for (int m = 0; m < 2; m++)
#pragma unroll
            for (int i = 0; i < 4; i++) c[m][i] = 0.f;
#pragma unroll 4
        for (int kb = 0; kb < 64; kb++) {
            u32 b0 = __ldg(&g_pW2t[(kb * 8 + tg) * AD + w * 8 + g]);
            u32 b1 = __ldg(&g_pW2t[(kb * 8 + tg + 4) * AD + w * 8 + g]);
            int k = kb * 8 + tg;
#pragma unroll
            for (int m = 0; m < 2; m++) {
                int r = m * 16 + g;
                u32 a0 = __float_as_uint(sP[r * 516 + k]);
                u32 a1 = __float_as_uint(sP[(r + 8) * 516 + k]);
                u32 a2 = __float_as_uint(sP[r * 516 + k + 4]);
                u32 a3 = __float_as_uint(sP[(r + 8) * 516 + k + 4]);
                mma8(c[m][0], c[m][1], c[m][2], c[m][3], a0, a1, a2, a3, b0, b1);
            }
        }
        float2 bias = *(const float2*)&pb2[w * 8 + 2 * tg];
        int col = w * 8 + 2 * tg;
#pragma unroll
        for (int m = 0; m < 2; m++) {
            long long r = n0 + m * 16 + g;
            float2 lo, hi;
            lo.x = c[m][0] + bias.x;
            lo.y = c[m][1] + bias.y;
            hi.x = c[m][2] + bias.x;
            hi.y = c[m][3] + bias.y;
            *(float2*)&out[r * AD + col] = lo;
            *(float2*)&out[(r + 8) * AD + col] = hi;
        }
    }
    __syncthreads();

    // ---- value layer 1 (tensor, overwrites sP)
    head_l1_mma(g_vW1t, vb1, sH, sP, w, g, tg);
    __syncthreads();

    // ---- value layer 2: 8 warps x 4 rows; 8-lane strided dots + shfl reduce
    {
        int row = w * 4 + (lane >> 3);
        int k0 = lane & 7;
        float s = 0.f;
#pragma unroll
        for (int k = k0; k < PD; k += 8) s += sP[row * 516 + k] * __ldg(&vW2[k]);
        s += __shfl_down_sync(0xffffffffu, s, 4);
        s += __shfl_down_sync(0xffffffffu, s, 2);
        s += __shfl_down_sync(0xffffffffu, s, 1);
        if (k0 == 0) out[(long long)NN * AD + n0 + row] = s + __ldg(&vb2[0]);
    }
}

// ---------------------------------------------------------------------------
// Host side.
// ---------------------------------------------------------------------------
extern "C" void kernel_launch(void* const* d_in, const int* in_sizes, int n_in,
                              void* d_out, int out_size) {
    const float* feat = (const float*)d_in[0];
    const int* ei = (const int*)d_in[1];  // int32 (JAX x64-off)
    const float* W1 = (const float*)d_in[2];
    const float* b1 = (const float*)d_in[3];
    const float* W2 = (const float*)d_in[4];
    const float* b2 = (const float*)d_in[5];
    const float* pW1 = (const float*)d_in[6];
    const float* pb1 = (const float*)d_in[7];
    const float* pW2 = (const float*)d_in[8];
    const float* pb2 = (const float*)d_in[9];
    const float* vW1 = (const float*)d_in[10];
    const float* vb1 = (const float*)d_in[11];
    const float* vW2 = (const float*)d_in[12];
    const float* vb2 = (const float*)d_in[13];
    float* out = (float*)d_out;

    const int* src = ei;       // edge_index[0]
    const int* dst = ei + NE;  // edge_index[1]

    static int smem_set = 0;
    const int HEAD_SMEM = (32 * 36 + 32 * 516) * 4;  // 70656 B
    if (!smem_set) {
        cudaFuncSetAttribute(k_head, cudaFuncAttributeMaxDynamicSharedMemorySize,
                             HEAD_SMEM);
        smem_set = 1;
    }

    // ---- CSR build + weight pre-conversion
    k_zero<<<(NN + 255) / 256, 256>>>();
    k_hist<<<(NE + 255) / 256, 256>>>(dst);
    k_bsum<<<NB_SCAN, 256>>>();
    k_scanb<<<1, 128>>>();
    k_off<<<NB_SCAN, 1024>>>();  // offsets + cursors + dinv
    k_fill<<<(NE + 255) / 256, 256>>>(src, dst);
    k_cvtw<<<(PD * AD + 255) / 256, 256>>>(pW1, pW2, vW1);

    // ---- conv1: buf1 = xs1 ; buf2 = agg1 (gather)
    k_gemm1<<<(NN + 63) / 64, 256>>>(feat, W1);
    k_gather<<<(NN + 15) / 16, 256>>>();

    // ---- conv2: buf1 = xs2 ; buf2 = agg2 (gather)
    k_gemm2<<<(NN + 63) / 64, 256>>>(W2, b1);
    k_gather<<<(NN + 15) / 16, 256>>>();

    // ---- heads (tf32 tensor cores; reads relu(buf2 + b2))
    k_head<<<(NN + 31) / 32, 256, HEAD_SMEM>>>(b2, pb1, pb2, vb1, vW2, vb2, out);
}